// round 2
// baseline (speedup 1.0000x reference)
#include <cuda_runtime.h>
#include <math.h>

#define BATCH 4
#define C_DIM 512
#define HW    4096
#define CHW   ((size_t)C_DIM * HW)       // 2,097,152 elems per batch per feature map
#define ATT_STRIDE ((size_t)HW * HW)     // 16,777,216 elems per batch

// ---------------- scratch (static device globals; no allocations) ----------------
__device__ float g_norm[BATCH * CHW];            // 32 MB
__device__ float g_F   [BATCH * CHW];            // 32 MB
__device__ float g_G   [BATCH * CHW];            // 32 MB
__device__ float g_H   [BATCH * CHW];            // 32 MB
__device__ float g_att [BATCH * ATT_STRIDE];     // 268 MB (energy -> softmax in place)
__device__ float g_o1  [BATCH * CHW];            // 32 MB

// ---------------- instance norm (per (b,c) over 4096 spatial) ----------------
__global__ __launch_bounds__(256) void instnorm_kernel(const float* __restrict__ x,
                                                       float* __restrict__ y) {
    const int bc = blockIdx.x;                   // 0..B*C-1
    const float* xp = x + (size_t)bc * HW;
    float*       yp = y + (size_t)bc * HW;

    float s = 0.f, s2 = 0.f;
    float v[16];
    #pragma unroll
    for (int i = 0; i < 16; i++) {
        v[i] = xp[threadIdx.x + i * 256];
        s  += v[i];
        s2 += v[i] * v[i];
    }
    // block reduce (sum, sumsq)
    __shared__ float r1[8], r2[8];
    #pragma unroll
    for (int o = 16; o > 0; o >>= 1) {
        s  += __shfl_xor_sync(0xffffffffu, s,  o);
        s2 += __shfl_xor_sync(0xffffffffu, s2, o);
    }
    const int warp = threadIdx.x >> 5, lane = threadIdx.x & 31;
    if (lane == 0) { r1[warp] = s; r2[warp] = s2; }
    __syncthreads();
    if (warp == 0) {
        s  = (lane < 8) ? r1[lane] : 0.f;
        s2 = (lane < 8) ? r2[lane] : 0.f;
        #pragma unroll
        for (int o = 4; o > 0; o >>= 1) {
            s  += __shfl_xor_sync(0xffffffffu, s,  o);
            s2 += __shfl_xor_sync(0xffffffffu, s2, o);
        }
        if (lane == 0) { r1[0] = s; r2[0] = s2; }
    }
    __syncthreads();
    const float mean = r1[0] * (1.f / HW);
    const float var  = r2[0] * (1.f / HW) - mean * mean;
    const float inv  = rsqrtf(var + 1e-5f);
    #pragma unroll
    for (int i = 0; i < 16; i++)
        yp[threadIdx.x + i * 256] = (v[i] - mean) * inv;
}

// ---------------- generic fp32 GEMM: C[MxN] = op(A) * op(B) (+bias[m]) (+res) --------
// A logical [M,K]: TA=false -> A[m*K+k] ; TA=true -> A[k*M+m]
// B logical [K,N]: TB=false -> B[k*N+n] ; TB=true -> B[n*K+k]   (B stored [N,K] row-major)
// 128x128 tile, BK=8, 256 threads, 8x8 per thread. All dims multiples of 128/8 here.
#define EPI_NONE     0
#define EPI_BIAS     1
#define EPI_BIAS_RES 2

template<bool TA, bool TB, int EPI>
__global__ __launch_bounds__(256) void gemm_kernel(
    const float* __restrict__ A, const float* __restrict__ B, float* __restrict__ Cm,
    const float* __restrict__ bias, const float* __restrict__ res,
    int M, int N, int K, size_t sA, size_t sB, size_t sC, size_t sRes)
{
    __shared__ float As[8][128];
    __shared__ float Bs[8][128];

    const int b = blockIdx.z;
    A  += sA * b;
    B  += sB * b;
    Cm += sC * b;
    const float* resp = (EPI == EPI_BIAS_RES) ? (res + sRes * b) : nullptr;

    const int m0 = blockIdx.y * 128;
    const int n0 = blockIdx.x * 128;
    const int tid = threadIdx.x;
    const int ty = tid >> 4;         // 0..15
    const int tx = tid & 15;         // 0..15

    float acc[8][8];
    #pragma unroll
    for (int i = 0; i < 8; i++)
        #pragma unroll
        for (int j = 0; j < 8; j++) acc[i][j] = 0.f;

    for (int k0 = 0; k0 < K; k0 += 8) {
        // ---- load A tile into As[k][m] ----
        if (TA) {
            const int k  = tid >> 5;            // 0..7
            const int mp = (tid & 31) * 4;      // 0..124
            const float4 v = *reinterpret_cast<const float4*>(&A[(size_t)(k0 + k) * M + m0 + mp]);
            *reinterpret_cast<float4*>(&As[k][mp]) = v;
        } else {
            const int row = tid >> 1;           // 0..127
            const int kp  = (tid & 1) * 4;      // 0 or 4
            const float4 v = *reinterpret_cast<const float4*>(&A[(size_t)(m0 + row) * K + k0 + kp]);
            As[kp + 0][row] = v.x; As[kp + 1][row] = v.y;
            As[kp + 2][row] = v.z; As[kp + 3][row] = v.w;
        }
        // ---- load B tile into Bs[k][n] ----
        if (TB) {
            const int row = tid >> 1;           // n offset 0..127
            const int kp  = (tid & 1) * 4;
            const float4 v = *reinterpret_cast<const float4*>(&B[(size_t)(n0 + row) * K + k0 + kp]);
            Bs[kp + 0][row] = v.x; Bs[kp + 1][row] = v.y;
            Bs[kp + 2][row] = v.z; Bs[kp + 3][row] = v.w;
        } else {
            const int k  = tid >> 5;
            const int np = (tid & 31) * 4;
            const float4 v = *reinterpret_cast<const float4*>(&B[(size_t)(k0 + k) * N + n0 + np]);
            *reinterpret_cast<float4*>(&Bs[k][np]) = v;
        }
        __syncthreads();

        #pragma unroll
        for (int k = 0; k < 8; k++) {
            float ra[8], rb[8];
            #pragma unroll
            for (int i = 0; i < 8; i++) ra[i] = As[k][ty * 8 + i];
            #pragma unroll
            for (int j = 0; j < 8; j++) rb[j] = Bs[k][tx * 8 + j];
            #pragma unroll
            for (int i = 0; i < 8; i++)
                #pragma unroll
                for (int j = 0; j < 8; j++)
                    acc[i][j] += ra[i] * rb[j];
        }
        __syncthreads();
    }

    // ---- epilogue ----
    #pragma unroll
    for (int i = 0; i < 8; i++) {
        const int m = m0 + ty * 8 + i;
        const float bv = (EPI >= EPI_BIAS) ? bias[m] : 0.f;
        #pragma unroll
        for (int j = 0; j < 8; j += 4) {
            const int n = n0 + tx * 8 + j;
            float4 o;
            o.x = acc[i][j + 0] + bv;
            o.y = acc[i][j + 1] + bv;
            o.z = acc[i][j + 2] + bv;
            o.w = acc[i][j + 3] + bv;
            if (EPI == EPI_BIAS_RES) {
                const float4 r = *reinterpret_cast<const float4*>(&resp[(size_t)m * N + n]);
                o.x += r.x; o.y += r.y; o.z += r.z; o.w += r.w;
            }
            *reinterpret_cast<float4*>(&Cm[(size_t)m * N + n]) = o;
        }
    }
}

// ---------------- row softmax over 4096, in place ----------------
__global__ __launch_bounds__(256) void softmax_kernel(float* __restrict__ att) {
    float* p = att + (size_t)blockIdx.x * HW;
    const int t = threadIdx.x;
    float v[16];
    float mx = -INFINITY;
    #pragma unroll
    for (int i = 0; i < 16; i++) {
        v[i] = p[t + i * 256];
        mx = fmaxf(mx, v[i]);
    }
    __shared__ float sred[8];
    #pragma unroll
    for (int o = 16; o > 0; o >>= 1) mx = fmaxf(mx, __shfl_xor_sync(0xffffffffu, mx, o));
    const int warp = t >> 5, lane = t & 31;
    if (lane == 0) sred[warp] = mx;
    __syncthreads();
    if (warp == 0) {
        mx = (lane < 8) ? sred[lane] : -INFINITY;
        #pragma unroll
        for (int o = 4; o > 0; o >>= 1) mx = fmaxf(mx, __shfl_xor_sync(0xffffffffu, mx, o));
        if (lane == 0) sred[0] = mx;
    }
    __syncthreads();
    mx = sred[0];
    __syncthreads();

    float sum = 0.f;
    #pragma unroll
    for (int i = 0; i < 16; i++) {
        v[i] = __expf(v[i] - mx);
        sum += v[i];
    }
    #pragma unroll
    for (int o = 16; o > 0; o >>= 1) sum += __shfl_xor_sync(0xffffffffu, sum, o);
    if (lane == 0) sred[warp] = sum;
    __syncthreads();
    if (warp == 0) {
        sum = (lane < 8) ? sred[lane] : 0.f;
        #pragma unroll
        for (int o = 4; o > 0; o >>= 1) sum += __shfl_xor_sync(0xffffffffu, sum, o);
        if (lane == 0) sred[0] = sum;
    }
    __syncthreads();
    const float inv = 1.f / sred[0];
    #pragma unroll
    for (int i = 0; i < 16; i++) p[t + i * 256] = v[i] * inv;
}

// ---------------- launch ----------------
extern "C" void kernel_launch(void* const* d_in, const int* in_sizes, int n_in,
                              void* d_out, int out_size) {
    (void)in_sizes; (void)n_in; (void)out_size;
    const float* content = (const float*)d_in[0];
    const float* f_w = (const float*)d_in[1];
    const float* f_b = (const float*)d_in[2];
    const float* g_w = (const float*)d_in[3];
    const float* g_b = (const float*)d_in[4];
    const float* h_w = (const float*)d_in[5];
    const float* h_b = (const float*)d_in[6];
    const float* o_w = (const float*)d_in[7];
    const float* o_b = (const float*)d_in[8];
    float* out = (float*)d_out;

    float *norm, *F, *G, *Hm, *att, *o1;
    cudaGetSymbolAddress((void**)&norm, g_norm);
    cudaGetSymbolAddress((void**)&F,    g_F);
    cudaGetSymbolAddress((void**)&G,    g_G);
    cudaGetSymbolAddress((void**)&Hm,   g_H);
    cudaGetSymbolAddress((void**)&att,  g_att);
    cudaGetSymbolAddress((void**)&o1,   g_o1);

    // 1) instance norm
    instnorm_kernel<<<BATCH * C_DIM, 256>>>(content, norm);

    // 2) conv f,g on norm ; conv h on raw content   (M=512, N=4096, K=512)
    const dim3 convGrid(HW / 128, C_DIM / 128, BATCH);
    gemm_kernel<false, false, EPI_BIAS><<<convGrid, 256>>>(
        f_w, norm, F, f_b, nullptr, C_DIM, HW, C_DIM, 0, CHW, CHW, 0);
    gemm_kernel<false, false, EPI_BIAS><<<convGrid, 256>>>(
        g_w, norm, G, g_b, nullptr, C_DIM, HW, C_DIM, 0, CHW, CHW, 0);
    gemm_kernel<false, false, EPI_BIAS><<<convGrid, 256>>>(
        h_w, content, Hm, h_b, nullptr, C_DIM, HW, C_DIM, 0, CHW, CHW, 0);

    // 3) energy = F^T G   (M=4096, N=4096, K=512), A col-major (= F stored [C,HW])
    const dim3 eGrid(HW / 128, HW / 128, BATCH);
    gemm_kernel<true, false, EPI_NONE><<<eGrid, 256>>>(
        F, G, att, nullptr, nullptr, HW, HW, C_DIM, CHW, CHW, ATT_STRIDE, 0);

    // 4) softmax rows
    softmax_kernel<<<BATCH * HW, 256>>>(att);

    // 5) o1[c,m] = sum_n H[c,n] att[m,n]   (M=512, N=4096, K=4096, B stored [N,K])
    gemm_kernel<false, true, EPI_NONE><<<convGrid, 256>>>(
        Hm, att, o1, nullptr, nullptr, C_DIM, HW, HW, CHW, ATT_STRIDE, CHW, 0);

    // 6) out = o_w * o1 + o_b + content
    gemm_kernel<false, false, EPI_BIAS_RES><<<convGrid, 256>>>(
        o_w, o1, out, o_b, content, C_DIM, HW, C_DIM, 0, CHW, CHW, CHW);
}